// round 15
// baseline (speedup 1.0000x reference)
#include <cuda_runtime.h>
#include <cuda_bf16.h>
#include <math.h>
#include <stdint.h>

// Problem constants
#define N_NODES 200000
#define E_EDGES 200000
#define H 256
#define KDIM 512     // combined K: [x | h_sum]
#define JDIM 1024    // combined output cols (permuted gate interleave)

// ---------------------------------------------------------------------------
// Scratch (static __device__ — no cudaMalloc anywhere)
// ---------------------------------------------------------------------------
__device__ float g_hsum[(size_t)N_NODES * H];          // 204.8 MB
__device__ float g_csum[(size_t)N_NODES * H];          // 204.8 MB
__device__ __nv_bfloat16 g_Bh[JDIM * KDIM];            // 1 MB (hi split, permuted rows)
__device__ __nv_bfloat16 g_Bl[JDIM * KDIM];            // 1 MB (lo split, permuted rows)

// ---------------------------------------------------------------------------
// 1) Split + permute weights into bf16 hi/lo. Permuted row jj = q*4 + g,
//    g in {0:i, 1:o, 2:u, 3:f}; cols k: [0,256)=W-part, [256,512)=U-part.
// ---------------------------------------------------------------------------
__global__ void build_B_kernel(const float* __restrict__ W_iou,
                               const float* __restrict__ U_iou,
                               const float* __restrict__ U_f_w) {
    int idx = blockIdx.x * blockDim.x + threadIdx.x;
    if (idx >= JDIM * KDIM) return;
    int jj = idx / KDIM;
    int k  = idx % KDIM;
    int q = jj >> 2;
    int g = jj & 3;
    float v;
    if (g < 3) {
        int row = g * 256 + q;
        v = (k < 256) ? W_iou[row * 256 + k] : U_iou[row * 256 + (k - 256)];
    } else {
        v = (k < 256) ? 0.0f : U_f_w[q * 256 + (k - 256)];
    }
    __nv_bfloat16 hi = __float2bfloat16(v);
    float lo = v - __bfloat162float(hi);
    g_Bh[idx] = hi;
    g_Bl[idx] = __float2bfloat16(lo);
}

// ---------------------------------------------------------------------------
// 2) Zero accumulators
// ---------------------------------------------------------------------------
__global__ void zero_sums_kernel() {
    size_t i = (size_t)blockIdx.x * blockDim.x + threadIdx.x;
    size_t n4 = (size_t)N_NODES * H / 4;
    if (i < n4) {
        ((float4*)g_hsum)[i] = make_float4(0.f, 0.f, 0.f, 0.f);
        ((float4*)g_csum)[i] = make_float4(0.f, 0.f, 0.f, 0.f);
    }
}

// ---------------------------------------------------------------------------
// 3) Scatter-add children into parents
// ---------------------------------------------------------------------------
__global__ void scatter_kernel(const float* __restrict__ h,
                               const float* __restrict__ c,
                               const int* __restrict__ src,
                               const int* __restrict__ dst) {
    size_t t = (size_t)blockIdx.x * blockDim.x + threadIdx.x;
    if (t >= (size_t)E_EDGES * (H / 4)) return;
    int e = (int)(t >> 6);
    int q = (int)(t & 63);
    int s = src[e];
    int d = dst[e];
    float4 hv = ((const float4*)h)[(size_t)s * 64 + q];
    float4 cv = ((const float4*)c)[(size_t)s * 64 + q];
    float* hd = &g_hsum[(size_t)d * H + q * 4];
    float* cd = &g_csum[(size_t)d * H + q * 4];
    atomicAdd(hd + 0, hv.x); atomicAdd(hd + 1, hv.y);
    atomicAdd(hd + 2, hv.z); atomicAdd(hd + 3, hv.w);
    atomicAdd(cd + 0, cv.x); atomicAdd(cd + 1, cv.y);
    atomicAdd(cd + 2, cv.z); atomicAdd(cd + 3, cv.w);
}

// ---------------------------------------------------------------------------
// 4) Fused warp-MMA (HMMA) GEMM + gate epilogue.
//    CTA tile 128 rows x 64 permuted cols (=16 h-cols x 4 gates) -> 3 CTAs/SM.
//    8 warps as 4m x 2n, warp tile 32x32. K=512 in 8 slabs of 64.
//    Per k-step: AhBh + AlBh + AhBl (error-compensated bf16).
// ---------------------------------------------------------------------------
#define TBM 128
#define TBJ 64
#define BK  64
#define NSLAB (KDIM / BK)
#define APAD 72                 // halves per row (64 + 8 pad) -> conflict-free
#define TROWB (APAD * 2)        // 144 bytes per tile row
#define SM_AH 0
#define SM_AL (SM_AH + TBM * TROWB)          // 18432
#define SM_BH (SM_AL + TBM * TROWB)          // 36864
#define SM_BL (SM_BH + TBJ * TROWB)          // 46080
#define SM_BYTES (SM_BL + TBJ * TROWB)       // 55296
#define PRELD 68                // floats per row in epilogue staging (34816 B)

__device__ __forceinline__ uint32_t smem_u32(const void* p) {
    uint32_t a;
    asm("{ .reg .u64 t; cvta.to.shared.u64 t, %1; cvt.u32.u64 %0, t; }" : "=r"(a) : "l"(p));
    return a;
}

#define LDSM4(r0, r1, r2, r3, addr) \
    asm volatile("ldmatrix.sync.aligned.m8n8.x4.shared.b16 {%0,%1,%2,%3}, [%4];" \
        : "=r"(r0), "=r"(r1), "=r"(r2), "=r"(r3) : "r"(addr))

__device__ __forceinline__ void mma16816(float* d, const uint32_t* a, const uint32_t* b) {
    asm volatile(
        "mma.sync.aligned.m16n8k16.row.col.f32.bf16.bf16.f32 "
        "{%0,%1,%2,%3}, {%4,%5,%6,%7}, {%8,%9}, {%0,%1,%2,%3};"
        : "+f"(d[0]), "+f"(d[1]), "+f"(d[2]), "+f"(d[3])
        : "r"(a[0]), "r"(a[1]), "r"(a[2]), "r"(a[3]), "r"(b[0]), "r"(b[1]));
}

__device__ __forceinline__ uint32_t pack_bf16x2(float a, float b) {
    __nv_bfloat162 t = __floats2bfloat162_rn(a, b);
    return *reinterpret_cast<uint32_t*>(&t);
}

__global__ __launch_bounds__(256, 3) void gemm_fused_kernel(
    const float* __restrict__ x,
    const float* __restrict__ b_iou,
    const float* __restrict__ U_f_b,
    float* __restrict__ out)
{
    extern __shared__ char smem[];
    __nv_bfloat16* sAh = (__nv_bfloat16*)(smem + SM_AH);
    __nv_bfloat16* sAl = (__nv_bfloat16*)(smem + SM_AL);
    __nv_bfloat16* sBh = (__nv_bfloat16*)(smem + SM_BH);
    __nv_bfloat16* sBl = (__nv_bfloat16*)(smem + SM_BL);
    const uint32_t sb = smem_u32(smem);

    const int tid = threadIdx.x;
    const int wid = tid >> 5;
    const int lid = tid & 31;
    const int gq = lid >> 2;       // quad-pair group 0..7
    const int tq = lid & 3;        // 0..3
    const int wm = wid >> 1;       // 0..3 : warp row block (32 rows)
    const int wn = wid & 1;        // 0..1 : warp col block (32 cols)
    const int cb = blockIdx.x;     // 0..15 : 16 h-cols each
    const int row0 = blockIdx.y * TBM;

    // ldmatrix lane offsets (bytes within a tile) — validated layout.
    const uint32_t aLane = (uint32_t)((lid & 15) * TROWB + ((lid & 16) ? 16 : 0));
    const uint32_t bLane = (uint32_t)(((lid & 7) + ((lid & 16) >> 1)) * TROWB + ((lid & 8) ? 16 : 0));

    float acc[2][4][4];
#pragma unroll
    for (int m = 0; m < 2; ++m)
#pragma unroll
        for (int n = 0; n < 4; ++n)
#pragma unroll
            for (int v = 0; v < 4; ++v) acc[m][n][v] = 0.f;

#pragma unroll 1
    for (int slab = 0; slab < NSLAB; ++slab) {
        if (slab) __syncthreads();

        // --- A slab: 128x64 fp32 -> hi/lo bf16, padded SMEM ---
        const float* Asrc = (slab < 4) ? x : g_hsum;
        const int kbA = (slab & 3) * BK;
        const int kbB = slab * BK;
#pragma unroll
        for (int it = 0; it < 8; ++it) {
            int f = tid + 256 * it;        // 0..2047
            int r = f >> 4;
            int kq = f & 15;
            int grow = row0 + r;
            float4 v = make_float4(0.f, 0.f, 0.f, 0.f);
            if (grow < N_NODES)
                v = *(const float4*)&Asrc[(size_t)grow * 256 + kbA + kq * 4];
            uint32_t h01 = pack_bf16x2(v.x, v.y);
            uint32_t h23 = pack_bf16x2(v.z, v.w);
            __nv_bfloat162 hh01 = *(__nv_bfloat162*)&h01;
            __nv_bfloat162 hh23 = *(__nv_bfloat162*)&h23;
            uint32_t l01 = pack_bf16x2(v.x - __bfloat162float(hh01.x),
                                       v.y - __bfloat162float(hh01.y));
            uint32_t l23 = pack_bf16x2(v.z - __bfloat162float(hh23.x),
                                       v.w - __bfloat162float(hh23.y));
            int o = r * APAD + kq * 4;
            *(uint2*)&sAh[o] = make_uint2(h01, h23);
            *(uint2*)&sAl[o] = make_uint2(l01, l23);
        }

        // --- B slab: pre-split bf16 hi/lo, 64 rows x 64 halves each ---
#pragma unroll
        for (int it = 0; it < 4; ++it) {
            int f = tid + 256 * it;        // 0..1023 ; [0,512)=hi, [512,1024)=lo
            int r = (f >> 3) & 63;
            int kq = f & 7;
            const __nv_bfloat16* src = (f < 512) ? g_Bh : g_Bl;
            __nv_bfloat16* dstp = (f < 512) ? sBh : sBl;
            uint4 v = *(const uint4*)&src[(size_t)(cb * TBJ + r) * KDIM + kbB + kq * 8];
            *(uint4*)&dstp[r * APAD + kq * 8] = v;
        }
        __syncthreads();

        const uint32_t uAh = sb + SM_AH;
        const uint32_t uAl = sb + SM_AL;
        const uint32_t uBh = sb + SM_BH;
        const uint32_t uBl = sb + SM_BL;

        // --- MMA over 4 k-steps of 16 (fragments via ldmatrix.x4) ---
#pragma unroll
        for (int ks = 0; ks < 4; ++ks) {
            const uint32_t kb2 = (uint32_t)(ks * 32);   // 16 halves = 32 bytes
            uint32_t afr[2][4], al[2][4], bfr[4][2];
            // Ah fragments: 2 ldmatrix.x4
#pragma unroll
            for (int m = 0; m < 2; ++m)
                LDSM4(afr[m][0], afr[m][1], afr[m][2], afr[m][3],
                      uAh + (uint32_t)((wm * 32 + m * 16) * TROWB) + aLane + kb2);
            // Bh fragments: 2 ldmatrix.x4 (2 n-tiles each)
#pragma unroll
            for (int np = 0; np < 2; ++np)
                LDSM4(bfr[np * 2][0], bfr[np * 2][1], bfr[np * 2 + 1][0], bfr[np * 2 + 1][1],
                      uBh + (uint32_t)((wn * 32 + np * 16) * TROWB) + bLane + kb2);
            // pass 1: Ah * Bh
#pragma unroll
            for (int m = 0; m < 2; ++m)
#pragma unroll
                for (int n = 0; n < 4; ++n)
                    mma16816(acc[m][n], afr[m], bfr[n]);
            // Al fragments, pass 2: Al * Bh
#pragma unroll
            for (int m = 0; m < 2; ++m)
                LDSM4(al[m][0], al[m][1], al[m][2], al[m][3],
                      uAl + (uint32_t)((wm * 32 + m * 16) * TROWB) + aLane + kb2);
#pragma unroll
            for (int m = 0; m < 2; ++m)
#pragma unroll
                for (int n = 0; n < 4; ++n)
                    mma16816(acc[m][n], al[m], bfr[n]);
            // Bl fragments (overwrite), pass 3: Ah * Bl
#pragma unroll
            for (int np = 0; np < 2; ++np)
                LDSM4(bfr[np * 2][0], bfr[np * 2][1], bfr[np * 2 + 1][0], bfr[np * 2 + 1][1],
                      uBl + (uint32_t)((wn * 32 + np * 16) * TROWB) + bLane + kb2);
#pragma unroll
            for (int m = 0; m < 2; ++m)
#pragma unroll
                for (int n = 0; n < 4; ++n)
                    mma16816(acc[m][n], afr[m], bfr[n]);
        }
    }

    // --- stage accumulators into SMEM (overlays tile buffers) ---
    __syncthreads();
    float* pre = (float*)smem;     // [128][PRELD]
#pragma unroll
    for (int m = 0; m < 2; ++m)
#pragma unroll
        for (int n = 0; n < 4; ++n) {
            int r = wm * 32 + m * 16 + gq;
            int cc = wn * 32 + n * 8 + tq * 2;
            *(float2*)&pre[r * PRELD + cc] = make_float2(acc[m][n][0], acc[m][n][1]);
            *(float2*)&pre[(r + 8) * PRELD + cc] = make_float2(acc[m][n][2], acc[m][n][3]);
        }
    __syncthreads();

    // --- gate epilogue + coalesced stores (16 h-cols per CTA) ---
    const int qd = tid & 15;           // h-col within tile
    const int rr = tid >> 4;           // 0..15
    const int Q = cb * 16 + qd;
    const float bi = __ldg(&b_iou[Q]);
    const float bo = __ldg(&b_iou[256 + Q]);
    const float bu = __ldg(&b_iou[512 + Q]);
    const float bf = __ldg(&U_f_b[Q]);
#pragma unroll
    for (int i = 0; i < 8; ++i) {
        int r = rr + 16 * i;
        int grow = row0 + r;
        if (grow >= N_NODES) continue;
        float4 p = *(const float4*)&pre[r * PRELD + qd * 4];   // {i,o,u,f}
        float iv = p.x + bi;
        float ov = p.y + bo;
        float uv = p.z + bu;
        float fv = p.w + bf;
        float cs = g_csum[(size_t)grow * 256 + Q];
        float sig_i = 1.0f / (1.0f + __expf(-iv));
        float sig_o = 1.0f / (1.0f + __expf(-ov));
        float sig_f = 1.0f / (1.0f + __expf(-fv));
        float c_new = sig_i * tanhf(uv) + sig_f * cs;
        float h_new = sig_o * tanhf(c_new);
        out[(size_t)grow * 256 + Q] = h_new;
        out[(size_t)N_NODES * 256 + (size_t)grow * 256 + Q] = c_new;
    }
}

// ---------------------------------------------------------------------------
// kernel_launch
// ---------------------------------------------------------------------------
extern "C" void kernel_launch(void* const* d_in, const int* in_sizes, int n_in,
                              void* d_out, int out_size) {
    const float* x     = (const float*)d_in[0];
    const float* h     = (const float*)d_in[1];
    const float* c     = (const float*)d_in[2];
    const int*   src   = (const int*)d_in[3];
    const int*   dst   = (const int*)d_in[4];
    const float* W_iou = (const float*)d_in[5];
    const float* U_iou = (const float*)d_in[6];
    const float* b_iou = (const float*)d_in[7];
    const float* U_f_w = (const float*)d_in[8];
    const float* U_f_b = (const float*)d_in[9];
    float* out = (float*)d_out;

    cudaFuncSetAttribute(gemm_fused_kernel,
                         cudaFuncAttributeMaxDynamicSharedMemorySize, SM_BYTES);

    build_B_kernel<<<(JDIM * KDIM + 255) / 256, 256>>>(W_iou, U_iou, U_f_w);

    {
        size_t n4 = (size_t)N_NODES * H / 4;
        zero_sums_kernel<<<(unsigned)((n4 + 255) / 256), 256>>>();
    }
    {
        size_t nt = (size_t)E_EDGES * (H / 4);
        scatter_kernel<<<(unsigned)((nt + 255) / 256), 256>>>(h, c, src, dst);
    }
    {
        dim3 grid(JDIM / TBJ, (N_NODES + TBM - 1) / TBM);   // (16, 1563)
        gemm_fused_kernel<<<grid, 256, SM_BYTES>>>(x, b_iou, U_f_b, out);
    }
}

// round 16
// speedup vs baseline: 1.2143x; 1.2143x over previous
#include <cuda_runtime.h>
#include <cuda_bf16.h>
#include <math.h>
#include <stdint.h>

// Problem constants
#define N_NODES 200000
#define E_EDGES 200000
#define H 256
#define KDIM 512     // combined K: [x | h_sum]
#define JDIM 1024    // combined output cols (permuted gate interleave)

// ---------------------------------------------------------------------------
// Scratch (static __device__ — no cudaMalloc anywhere)
// ---------------------------------------------------------------------------
__device__ float g_hsum[(size_t)N_NODES * H];          // 204.8 MB
__device__ float g_csum[(size_t)N_NODES * H];          // 204.8 MB
__device__ __nv_bfloat16 g_Bh[JDIM * KDIM];            // 1 MB (hi split, permuted rows)
__device__ __nv_bfloat16 g_Bl[JDIM * KDIM];            // 1 MB (lo split, permuted rows)

// ---------------------------------------------------------------------------
// 1) Split + permute weights into bf16 hi/lo. Permuted row jj = q*4 + g,
//    g in {0:i, 1:o, 2:u, 3:f}; cols k: [0,256)=W-part, [256,512)=U-part.
// ---------------------------------------------------------------------------
__global__ void build_B_kernel(const float* __restrict__ W_iou,
                               const float* __restrict__ U_iou,
                               const float* __restrict__ U_f_w) {
    int idx = blockIdx.x * blockDim.x + threadIdx.x;
    if (idx >= JDIM * KDIM) return;
    int jj = idx / KDIM;
    int k  = idx % KDIM;
    int q = jj >> 2;
    int g = jj & 3;
    float v;
    if (g < 3) {
        int row = g * 256 + q;
        v = (k < 256) ? W_iou[row * 256 + k] : U_iou[row * 256 + (k - 256)];
    } else {
        v = (k < 256) ? 0.0f : U_f_w[q * 256 + (k - 256)];
    }
    __nv_bfloat16 hi = __float2bfloat16(v);
    float lo = v - __bfloat162float(hi);
    g_Bh[idx] = hi;
    g_Bl[idx] = __float2bfloat16(lo);
}

// ---------------------------------------------------------------------------
// 2) Zero accumulators
// ---------------------------------------------------------------------------
__global__ void zero_sums_kernel() {
    size_t i = (size_t)blockIdx.x * blockDim.x + threadIdx.x;
    size_t n4 = (size_t)N_NODES * H / 4;
    if (i < n4) {
        ((float4*)g_hsum)[i] = make_float4(0.f, 0.f, 0.f, 0.f);
        ((float4*)g_csum)[i] = make_float4(0.f, 0.f, 0.f, 0.f);
    }
}

// ---------------------------------------------------------------------------
// 3) Scatter-add children into parents
// ---------------------------------------------------------------------------
__global__ void scatter_kernel(const float* __restrict__ h,
                               const float* __restrict__ c,
                               const int* __restrict__ src,
                               const int* __restrict__ dst) {
    size_t t = (size_t)blockIdx.x * blockDim.x + threadIdx.x;
    if (t >= (size_t)E_EDGES * (H / 4)) return;
    int e = (int)(t >> 6);
    int q = (int)(t & 63);
    int s = src[e];
    int d = dst[e];
    float4 hv = ((const float4*)h)[(size_t)s * 64 + q];
    float4 cv = ((const float4*)c)[(size_t)s * 64 + q];
    float* hd = &g_hsum[(size_t)d * H + q * 4];
    float* cd = &g_csum[(size_t)d * H + q * 4];
    atomicAdd(hd + 0, hv.x); atomicAdd(hd + 1, hv.y);
    atomicAdd(hd + 2, hv.z); atomicAdd(hd + 3, hv.w);
    atomicAdd(cd + 0, cv.x); atomicAdd(cd + 1, cv.y);
    atomicAdd(cd + 2, cv.z); atomicAdd(cd + 3, cv.w);
}

// ---------------------------------------------------------------------------
// 4) Register-staged pipelined HMMA GEMM + fused gate epilogue.
//    CTA tile 128 rows x 128 permuted cols; 512 threads, 16 warps (8m x 2n),
//    warp tile 16x64; K=512 in 8 slabs of 64; SINGLE SMEM stage.
//    Slab s+1's LDGs are issued before slab s's MMA phase and land during it.
//    Per k-step: AhBh + AlBh + AhBl (error-compensated bf16).
// ---------------------------------------------------------------------------
#define TBM 128
#define TBJ 128
#define BK  64
#define NSLAB (KDIM / BK)
#define NTHREADS 512
#define APAD 72                 // halves per row (64 + 8 pad) -> conflict-free
#define TROWB (APAD * 2)        // 144 bytes per tile row
#define SM_AH 0
#define SM_AL (SM_AH + TBM * TROWB)          // 18432
#define SM_BH (SM_AL + TBM * TROWB)          // 36864
#define SM_BL (SM_BH + TBJ * TROWB)          // 55296
#define SM_BYTES (SM_BL + TBJ * TROWB)       // 73728
#define PRELD 132               // floats per row in epilogue staging (67584 B)

__device__ __forceinline__ uint32_t smem_u32(const void* p) {
    uint32_t a;
    asm("{ .reg .u64 t; cvta.to.shared.u64 t, %1; cvt.u32.u64 %0, t; }" : "=r"(a) : "l"(p));
    return a;
}

#define LDSM4(r0, r1, r2, r3, addr) \
    asm volatile("ldmatrix.sync.aligned.m8n8.x4.shared.b16 {%0,%1,%2,%3}, [%4];" \
        : "=r"(r0), "=r"(r1), "=r"(r2), "=r"(r3) : "r"(addr))

__device__ __forceinline__ void mma16816(float* d, const uint32_t* a, const uint32_t* b) {
    asm volatile(
        "mma.sync.aligned.m16n8k16.row.col.f32.bf16.bf16.f32 "
        "{%0,%1,%2,%3}, {%4,%5,%6,%7}, {%8,%9}, {%0,%1,%2,%3};"
        : "+f"(d[0]), "+f"(d[1]), "+f"(d[2]), "+f"(d[3])
        : "r"(a[0]), "r"(a[1]), "r"(a[2]), "r"(a[3]), "r"(b[0]), "r"(b[1]));
}

__device__ __forceinline__ uint32_t pack_bf16x2(float a, float b) {
    __nv_bfloat162 t = __floats2bfloat162_rn(a, b);
    return *reinterpret_cast<uint32_t*>(&t);
}

__global__ __launch_bounds__(NTHREADS, 1) void gemm_fused_kernel(
    const float* __restrict__ x,
    const float* __restrict__ b_iou,
    const float* __restrict__ U_f_b,
    float* __restrict__ out)
{
    extern __shared__ char smem[];
    __nv_bfloat16* sAh = (__nv_bfloat16*)(smem + SM_AH);
    __nv_bfloat16* sAl = (__nv_bfloat16*)(smem + SM_AL);
    __nv_bfloat16* sBh = (__nv_bfloat16*)(smem + SM_BH);
    __nv_bfloat16* sBl = (__nv_bfloat16*)(smem + SM_BL);
    const uint32_t sb = smem_u32(smem);

    const int tid = threadIdx.x;
    const int wid = tid >> 5;
    const int lid = tid & 31;
    const int gq = lid >> 2;       // 0..7
    const int tq = lid & 3;        // 0..3
    const int wm = wid >> 1;       // 0..7 : warp row block (16 rows)
    const int wn = wid & 1;        // 0..1 : warp col block (64 cols)
    const int cb = blockIdx.x;     // 0..7 : 32 h-cols each
    const int row0 = blockIdx.y * TBM;

    // ldmatrix lane offsets (bytes within a tile) — validated layout.
    const uint32_t aLane = (uint32_t)((lid & 15) * TROWB + ((lid & 16) ? 16 : 0));
    const uint32_t bLane = (uint32_t)(((lid & 7) + ((lid & 16) >> 1)) * TROWB + ((lid & 8) ? 16 : 0));

    // Per-thread load slots (512 threads):
    //  A: 2048 float4 -> 4/thread ; B: 2048 uint4 (hi+lo) -> 4/thread
    const int arow[1] = {0};  (void)arow;
    float4 va[4];              // prefetched A fp32 (converted in place below)
    uint4  vb[4];              // prefetched B bf16 hi/lo
    uint2  cah[4], cal[4];     // converted A hi/lo

    float acc[8][4];
#pragma unroll
    for (int n = 0; n < 8; ++n)
#pragma unroll
        for (int v = 0; v < 4; ++v) acc[n][v] = 0.f;

    // ---- LDG slab -> registers ----
    auto load_regs = [&](int slab) {
        const float* Asrc = (slab < 4) ? x : g_hsum;
        const int kbA = (slab & 3) * BK;
        const int kbB = slab * BK;
#pragma unroll
        for (int it = 0; it < 4; ++it) {
            int f = tid + NTHREADS * it;   // 0..2047
            int r = f >> 4;
            int kq = f & 15;
            int grow = row0 + r;
            va[it] = make_float4(0.f, 0.f, 0.f, 0.f);
            if (grow < N_NODES)
                va[it] = *(const float4*)&Asrc[(size_t)grow * 256 + kbA + kq * 4];
        }
#pragma unroll
        for (int it = 0; it < 4; ++it) {
            int f = tid + NTHREADS * it;   // 0..2047 ; [0,1024)=hi, rest lo
            int r = (f >> 3) & 127;
            int kq = f & 7;
            const __nv_bfloat16* src = (f < 1024) ? g_Bh : g_Bl;
            vb[it] = *(const uint4*)&src[(size_t)(cb * TBJ + r) * KDIM + kbB + kq * 8];
        }
    };

    // ---- convert prefetched A fp32 -> bf16 hi/lo pairs ----
    auto convert_regs = [&]() {
#pragma unroll
        for (int it = 0; it < 4; ++it) {
            float4 v = va[it];
            uint32_t h01 = pack_bf16x2(v.x, v.y);
            uint32_t h23 = pack_bf16x2(v.z, v.w);
            __nv_bfloat162 hh01 = *(__nv_bfloat162*)&h01;
            __nv_bfloat162 hh23 = *(__nv_bfloat162*)&h23;
            uint32_t l01 = pack_bf16x2(v.x - __bfloat162float(hh01.x),
                                       v.y - __bfloat162float(hh01.y));
            uint32_t l23 = pack_bf16x2(v.z - __bfloat162float(hh23.x),
                                       v.w - __bfloat162float(hh23.y));
            cah[it] = make_uint2(h01, h23);
            cal[it] = make_uint2(l01, l23);
        }
    };

    // ---- STS converted slab into SMEM ----
    auto store_stage = [&]() {
#pragma unroll
        for (int it = 0; it < 4; ++it) {
            int f = tid + NTHREADS * it;
            int r = f >> 4;
            int kq = f & 15;
            int o = r * APAD + kq * 4;
            *(uint2*)&sAh[o] = cah[it];
            *(uint2*)&sAl[o] = cal[it];
        }
#pragma unroll
        for (int it = 0; it < 4; ++it) {
            int f = tid + NTHREADS * it;
            int r = (f >> 3) & 127;
            int kq = f & 7;
            __nv_bfloat16* dstp = (f < 1024) ? sBh : sBl;
            *(uint4*)&dstp[r * APAD + kq * 8] = vb[it];
        }
    };

    // ---- prologue ----
    load_regs(0);
    convert_regs();

#pragma unroll 1
    for (int slab = 0; slab < NSLAB; ++slab) {
        if (slab) __syncthreads();     // previous MMA phase done reading SMEM
        store_stage();
        if (slab + 1 < NSLAB) load_regs(slab + 1);   // LDGs fly during MMA
        __syncthreads();

        const uint32_t uAh = sb + SM_AH;
        const uint32_t uAl = sb + SM_AL;
        const uint32_t uBh = sb + SM_BH;
        const uint32_t uBl = sb + SM_BL;
        const uint32_t rowA = (uint32_t)((wm * 16) * TROWB);
        const uint32_t rowB = (uint32_t)((wn * 64) * TROWB);

        // --- MMA over 4 k-steps of 16 (fragments via ldmatrix.x4) ---
#pragma unroll
        for (int ks = 0; ks < 4; ++ks) {
            const uint32_t kb2 = (uint32_t)(ks * 32);
            uint32_t afr[4], al[4], bfr[8][2];
            LDSM4(afr[0], afr[1], afr[2], afr[3], uAh + rowA + aLane + kb2);
#pragma unroll
            for (int np = 0; np < 4; ++np)
                LDSM4(bfr[np * 2][0], bfr[np * 2][1], bfr[np * 2 + 1][0], bfr[np * 2 + 1][1],
                      uBh + rowB + (uint32_t)(np * 16 * TROWB) + bLane + kb2);
            // pass 1: Ah * Bh
#pragma unroll
            for (int n = 0; n < 8; ++n)
                mma16816(acc[n], afr, bfr[n]);
            // pass 2: Al * Bh
            LDSM4(al[0], al[1], al[2], al[3], uAl + rowA + aLane + kb2);
#pragma unroll
            for (int n = 0; n < 8; ++n)
                mma16816(acc[n], al, bfr[n]);
            // pass 3: Ah * Bl
#pragma unroll
            for (int np = 0; np < 4; ++np)
                LDSM4(bfr[np * 2][0], bfr[np * 2][1], bfr[np * 2 + 1][0], bfr[np * 2 + 1][1],
                      uBl + rowB + (uint32_t)(np * 16 * TROWB) + bLane + kb2);
#pragma unroll
            for (int n = 0; n < 8; ++n)
                mma16816(acc[n], afr, bfr[n]);
        }

        // Convert the prefetched next slab (LDG latency已 elapsed under MMA)
        if (slab + 1 < NSLAB) convert_regs();
    }

    // --- stage accumulators into SMEM (overlays tile buffers) ---
    __syncthreads();
    float* pre = (float*)smem;     // [128][PRELD]
#pragma unroll
    for (int n = 0; n < 8; ++n) {
        int r = wm * 16 + gq;
        int cc = wn * 64 + n * 8 + tq * 2;
        *(float2*)&pre[r * PRELD + cc] = make_float2(acc[n][0], acc[n][1]);
        *(float2*)&pre[(r + 8) * PRELD + cc] = make_float2(acc[n][2], acc[n][3]);
    }
    __syncthreads();

    // --- gate epilogue + coalesced stores (512 threads: 8 rows each) ---
    const int q = tid & 31;
    const int Q = cb * 32 + q;
    const float bi = __ldg(&b_iou[Q]);
    const float bo = __ldg(&b_iou[256 + Q]);
    const float bu = __ldg(&b_iou[512 + Q]);
    const float bf = __ldg(&U_f_b[Q]);
#pragma unroll
    for (int i = 0; i < 8; ++i) {
        int r = (tid >> 5) + 16 * i;
        int grow = row0 + r;
        if (grow >= N_NODES) continue;
        float4 p = *(const float4*)&pre[r * PRELD + q * 4];   // {i,o,u,f}
        float iv = p.x + bi;
        float ov = p.y + bo;
        float uv = p.z + bu;
        float fv = p.w + bf;
        float cs = g_csum[(size_t)grow * 256 + Q];
        float sig_i = 1.0f / (1.0f + __expf(-iv));
        float sig_o = 1.0f / (1.0f + __expf(-ov));
        float sig_f = 1.0f / (1.0f + __expf(-fv));
        float c_new = sig_i * tanhf(uv) + sig_f * cs;
        float h_new = sig_o * tanhf(c_new);
        out[(size_t)grow * 256 + Q] = h_new;
        out[(size_t)N_NODES * 256 + (size_t)grow * 256 + Q] = c_new;
    }
}

// ---------------------------------------------------------------------------
// kernel_launch
// ---------------------------------------------------------------------------
extern "C" void kernel_launch(void* const* d_in, const int* in_sizes, int n_in,
                              void* d_out, int out_size) {
    const float* x     = (const float*)d_in[0];
    const float* h     = (const float*)d_in[1];
    const float* c     = (const float*)d_in[2];
    const int*   src   = (const int*)d_in[3];
    const int*   dst   = (const int*)d_in[4];
    const float* W_iou = (const float*)d_in[5];
    const float* U_iou = (const float*)d_in[6];
    const float* b_iou = (const float*)d_in[7];
    const float* U_f_w = (const float*)d_in[8];
    const float* U_f_b = (const float*)d_in[9];
    float* out = (float*)d_out;

    cudaFuncSetAttribute(gemm_fused_kernel,
                         cudaFuncAttributeMaxDynamicSharedMemorySize, SM_BYTES);

    build_B_kernel<<<(JDIM * KDIM + 255) / 256, 256>>>(W_iou, U_iou, U_f_w);

    {
        size_t n4 = (size_t)N_NODES * H / 4;
        zero_sums_kernel<<<(unsigned)((n4 + 255) / 256), 256>>>();
    }
    {
        size_t nt = (size_t)E_EDGES * (H / 4);
        scatter_kernel<<<(unsigned)((nt + 255) / 256), 256>>>(h, c, src, dst);
    }
    {
        dim3 grid(JDIM / TBJ, (N_NODES + TBM - 1) / TBM);   // (8, 1563)
        gemm_fused_kernel<<<grid, NTHREADS, SM_BYTES>>>(x, b_iou, U_f_b, out);
    }
}

// round 17
// speedup vs baseline: 1.5670x; 1.2904x over previous
#include <cuda_runtime.h>
#include <cuda_bf16.h>
#include <math.h>
#include <stdint.h>

// Problem constants
#define N_NODES 200000
#define E_EDGES 200000
#define H 256
#define KDIM 512     // combined K: [x | h_sum]
#define JDIM 1024    // combined output cols (permuted gate interleave)

// ---------------------------------------------------------------------------
// Scratch (static __device__ — no cudaMalloc anywhere)
// ---------------------------------------------------------------------------
__device__ float g_hsum[(size_t)N_NODES * H];          // 204.8 MB
__device__ float g_csum[(size_t)N_NODES * H];          // 204.8 MB
__device__ __nv_bfloat16 g_Bh[JDIM * KDIM];            // 1 MB (hi split, permuted rows)
__device__ __nv_bfloat16 g_Bl[JDIM * KDIM];            // 1 MB (lo split, permuted rows)

// ---------------------------------------------------------------------------
// 1) Split + permute weights into bf16 hi/lo. Permuted row jj = q*4 + g,
//    g in {0:i, 1:o, 2:u, 3:f}; cols k: [0,256)=W-part, [256,512)=U-part.
// ---------------------------------------------------------------------------
__global__ void build_B_kernel(const float* __restrict__ W_iou,
                               const float* __restrict__ U_iou,
                               const float* __restrict__ U_f_w) {
    int idx = blockIdx.x * blockDim.x + threadIdx.x;
    if (idx >= JDIM * KDIM) return;
    int jj = idx / KDIM;
    int k  = idx % KDIM;
    int q = jj >> 2;
    int g = jj & 3;
    float v;
    if (g < 3) {
        int row = g * 256 + q;
        v = (k < 256) ? W_iou[row * 256 + k] : U_iou[row * 256 + (k - 256)];
    } else {
        v = (k < 256) ? 0.0f : U_f_w[q * 256 + (k - 256)];
    }
    __nv_bfloat16 hi = __float2bfloat16(v);
    float lo = v - __bfloat162float(hi);
    g_Bh[idx] = hi;
    g_Bl[idx] = __float2bfloat16(lo);
}

// ---------------------------------------------------------------------------
// 2) Zero accumulators
// ---------------------------------------------------------------------------
__global__ void zero_sums_kernel() {
    size_t i = (size_t)blockIdx.x * blockDim.x + threadIdx.x;
    size_t n4 = (size_t)N_NODES * H / 4;
    if (i < n4) {
        ((float4*)g_hsum)[i] = make_float4(0.f, 0.f, 0.f, 0.f);
        ((float4*)g_csum)[i] = make_float4(0.f, 0.f, 0.f, 0.f);
    }
}

// ---------------------------------------------------------------------------
// 3) Scatter-add children into parents — vectorized red.global.add.v4.f32
//    (sm_90+ baseline PTX): 2 vector REDs per thread instead of 8 scalar.
// ---------------------------------------------------------------------------
__device__ __forceinline__ void red_add_v4(float* ptr, float4 v) {
    asm volatile("red.global.add.v4.f32 [%0], {%1, %2, %3, %4};"
                 :: "l"(ptr), "f"(v.x), "f"(v.y), "f"(v.z), "f"(v.w)
                 : "memory");
}

__global__ void scatter_kernel(const float* __restrict__ h,
                               const float* __restrict__ c,
                               const int* __restrict__ src,
                               const int* __restrict__ dst) {
    size_t t = (size_t)blockIdx.x * blockDim.x + threadIdx.x;
    if (t >= (size_t)E_EDGES * (H / 4)) return;
    int e = (int)(t >> 6);   // H/4 = 64 chunks per edge
    int q = (int)(t & 63);
    int s = src[e];
    int d = dst[e];
    float4 hv = ((const float4*)h)[(size_t)s * 64 + q];
    float4 cv = ((const float4*)c)[(size_t)s * 64 + q];
    red_add_v4(&g_hsum[(size_t)d * H + q * 4], hv);
    red_add_v4(&g_csum[(size_t)d * H + q * 4], cv);
}

// ---------------------------------------------------------------------------
// 4) Fused warp-MMA (HMMA) GEMM + gate epilogue. R14 winner — UNCHANGED.
//    CTA tile 128 rows x 128 permuted cols (=32 h-cols x 4 gates).
//    K=512 in 8 slabs of 64. Per k-step: AhBh + AlBh + AhBl (error-comp bf16).
// ---------------------------------------------------------------------------
#define TBM 128
#define TBJ 128
#define BK  64
#define NSLAB (KDIM / BK)
#define APAD 72                 // halves per row (64 + 8 pad) -> conflict-free
#define TROWB (APAD * 2)        // 144 bytes per tile row
#define SM_AH 0
#define SM_AL (SM_AH + TBM * TROWB)          // 18432
#define SM_BH (SM_AL + TBM * TROWB)          // 36864
#define SM_BL (SM_BH + TBJ * TROWB)          // 55296
#define SM_BYTES (SM_BL + TBJ * TROWB)       // 73728
#define PRELD 132               // floats per row in epilogue staging

__device__ __forceinline__ uint32_t smem_u32(const void* p) {
    uint32_t a;
    asm("{ .reg .u64 t; cvta.to.shared.u64 t, %1; cvt.u32.u64 %0, t; }" : "=r"(a) : "l"(p));
    return a;
}

#define LDSM4(r0, r1, r2, r3, addr) \
    asm volatile("ldmatrix.sync.aligned.m8n8.x4.shared.b16 {%0,%1,%2,%3}, [%4];" \
        : "=r"(r0), "=r"(r1), "=r"(r2), "=r"(r3) : "r"(addr))

__device__ __forceinline__ void mma16816(float* d, const uint32_t* a, const uint32_t* b) {
    asm volatile(
        "mma.sync.aligned.m16n8k16.row.col.f32.bf16.bf16.f32 "
        "{%0,%1,%2,%3}, {%4,%5,%6,%7}, {%8,%9}, {%0,%1,%2,%3};"
        : "+f"(d[0]), "+f"(d[1]), "+f"(d[2]), "+f"(d[3])
        : "r"(a[0]), "r"(a[1]), "r"(a[2]), "r"(a[3]), "r"(b[0]), "r"(b[1]));
}

__device__ __forceinline__ uint32_t pack_bf16x2(float a, float b) {
    __nv_bfloat162 t = __floats2bfloat162_rn(a, b);
    return *reinterpret_cast<uint32_t*>(&t);
}

__global__ __launch_bounds__(256, 2) void gemm_fused_kernel(
    const float* __restrict__ x,
    const float* __restrict__ b_iou,
    const float* __restrict__ U_f_b,
    float* __restrict__ out)
{
    extern __shared__ char smem[];
    __nv_bfloat16* sAh = (__nv_bfloat16*)(smem + SM_AH);
    __nv_bfloat16* sAl = (__nv_bfloat16*)(smem + SM_AL);
    __nv_bfloat16* sBh = (__nv_bfloat16*)(smem + SM_BH);
    __nv_bfloat16* sBl = (__nv_bfloat16*)(smem + SM_BL);
    const uint32_t sb = smem_u32(smem);

    const int tid = threadIdx.x;
    const int wid = tid >> 5;
    const int lid = tid & 31;
    const int gq = lid >> 2;       // quad-pair group 0..7
    const int tq = lid & 3;        // 0..3
    const int wm = wid >> 1;       // 0..3 : warp row block (32 rows)
    const int wn = wid & 1;        // 0..1 : warp col block (64 cols)
    const int cb = blockIdx.x;     // 0..7 : 32 h-cols each
    const int row0 = blockIdx.y * TBM;

    // ldmatrix lane offsets (bytes within a tile) — validated layout.
    const uint32_t aLane = (uint32_t)((lid & 15) * TROWB + ((lid & 16) ? 16 : 0));
    const uint32_t bLane = (uint32_t)(((lid & 7) + ((lid & 16) >> 1)) * TROWB + ((lid & 8) ? 16 : 0));

    float acc[2][8][4];
#pragma unroll
    for (int m = 0; m < 2; ++m)
#pragma unroll
        for (int n = 0; n < 8; ++n)
#pragma unroll
            for (int v = 0; v < 4; ++v) acc[m][n][v] = 0.f;

#pragma unroll 1
    for (int slab = 0; slab < NSLAB; ++slab) {
        if (slab) __syncthreads();

        // --- A slab: 128x64 fp32 -> hi/lo bf16, padded SMEM ---
        const float* Asrc = (slab < 4) ? x : g_hsum;
        const int kbA = (slab & 3) * BK;
        const int kbB = slab * BK;
#pragma unroll
        for (int it = 0; it < 8; ++it) {
            int f = tid + 256 * it;        // 0..2047
            int r = f >> 4;
            int kq = f & 15;
            int grow = row0 + r;
            float4 v = make_float4(0.f, 0.f, 0.f, 0.f);
            if (grow < N_NODES)
                v = *(const float4*)&Asrc[(size_t)grow * 256 + kbA + kq * 4];
            uint32_t h01 = pack_bf16x2(v.x, v.y);
            uint32_t h23 = pack_bf16x2(v.z, v.w);
            __nv_bfloat162 hh01 = *(__nv_bfloat162*)&h01;
            __nv_bfloat162 hh23 = *(__nv_bfloat162*)&h23;
            uint32_t l01 = pack_bf16x2(v.x - __bfloat162float(hh01.x),
                                       v.y - __bfloat162float(hh01.y));
            uint32_t l23 = pack_bf16x2(v.z - __bfloat162float(hh23.x),
                                       v.w - __bfloat162float(hh23.y));
            int o = r * APAD + kq * 4;
            *(uint2*)&sAh[o] = make_uint2(h01, h23);
            *(uint2*)&sAl[o] = make_uint2(l01, l23);
        }

        // --- B slab: pre-split bf16 hi/lo, 128 rows x 64 halves each ---
#pragma unroll
        for (int it = 0; it < 8; ++it) {
            int f = tid + 256 * it;        // 0..2047 ; [0,1024)=hi, [1024,2048)=lo
            int r = (f >> 3) & 127;
            int kq = f & 7;
            const __nv_bfloat16* src = (f < 1024) ? g_Bh : g_Bl;
            __nv_bfloat16* dstp = (f < 1024) ? sBh : sBl;
            uint4 v = *(const uint4*)&src[(size_t)(cb * TBJ + r) * KDIM + kbB + kq * 8];
            *(uint4*)&dstp[r * APAD + kq * 8] = v;
        }
        __syncthreads();

        const uint32_t uAh = sb + SM_AH;
        const uint32_t uAl = sb + SM_AL;
        const uint32_t uBh = sb + SM_BH;
        const uint32_t uBl = sb + SM_BL;

        // --- MMA over 4 k-steps of 16 (fragments via ldmatrix.x4) ---
#pragma unroll
        for (int ks = 0; ks < 4; ++ks) {
            const uint32_t kb2 = (uint32_t)(ks * 32);   // 16 halves = 32 bytes
            uint32_t afr[2][4], al[2][4], bfr[8][2];
            // Ah fragments: 2 ldmatrix.x4
#pragma unroll
            for (int m = 0; m < 2; ++m)
                LDSM4(afr[m][0], afr[m][1], afr[m][2], afr[m][3],
                      uAh + (uint32_t)((wm * 32 + m * 16) * TROWB) + aLane + kb2);
            // Bh fragments: 4 ldmatrix.x4 (2 n-tiles each)
#pragma unroll
            for (int np = 0; np < 4; ++np)
                LDSM4(bfr[np * 2][0], bfr[np * 2][1], bfr[np * 2 + 1][0], bfr[np * 2 + 1][1],
                      uBh + (uint32_t)((wn * 64 + np * 16) * TROWB) + bLane + kb2);
            // pass 1: Ah * Bh
#pragma unroll
            for (int m = 0; m < 2; ++m)
#pragma unroll
                for (int n = 0; n < 8; ++n)
                    mma16816(acc[m][n], afr[m], bfr[n]);
            // Al fragments, pass 2: Al * Bh
#pragma unroll
            for (int m = 0; m < 2; ++m)
                LDSM4(al[m][0], al[m][1], al[m][2], al[m][3],
                      uAl + (uint32_t)((wm * 32 + m * 16) * TROWB) + aLane + kb2);
#pragma unroll
            for (int m = 0; m < 2; ++m)
#pragma unroll
                for (int n = 0; n < 8; ++n)
                    mma16816(acc[m][n], al[m], bfr[n]);
            // Bl fragments (overwrite), pass 3: Ah * Bl
#pragma unroll
            for (int np = 0; np < 4; ++np)
                LDSM4(bfr[np * 2][0], bfr[np * 2][1], bfr[np * 2 + 1][0], bfr[np * 2 + 1][1],
                      uBl + (uint32_t)((wn * 64 + np * 16) * TROWB) + bLane + kb2);
#pragma unroll
            for (int m = 0; m < 2; ++m)
#pragma unroll
                for (int n = 0; n < 8; ++n)
                    mma16816(acc[m][n], afr[m], bfr[n]);
        }
    }

    // --- stage accumulators into SMEM (overlays tile buffers) ---
    __syncthreads();
    float* pre = (float*)smem;     // [128][PRELD]
#pragma unroll
    for (int m = 0; m < 2; ++m)
#pragma unroll
        for (int n = 0; n < 8; ++n) {
            int r = wm * 32 + m * 16 + gq;
            int cc = wn * 64 + n * 8 + tq * 2;
            *(float2*)&pre[r * PRELD + cc] = make_float2(acc[m][n][0], acc[m][n][1]);
            *(float2*)&pre[(r + 8) * PRELD + cc] = make_float2(acc[m][n][2], acc[m][n][3]);
        }
    __syncthreads();

    // --- gate epilogue + coalesced stores ---
    const int q = tid & 31;
    const int Q = cb * 32 + q;
    const float bi = __ldg(&b_iou[Q]);
    const float bo = __ldg(&b_iou[256 + Q]);
    const float bu = __ldg(&b_iou[512 + Q]);
    const float bf = __ldg(&U_f_b[Q]);
#pragma unroll
    for (int i = 0; i < 16; ++i) {
        int r = (tid >> 5) + 8 * i;
        int grow = row0 + r;
        if (grow >= N_NODES) continue;
        float4 p = *(const float4*)&pre[r * PRELD + q * 4];   // {i,o,u,f}
        float iv = p.x + bi;
        float ov = p.y + bo;
        float uv = p.z + bu;
        float fv = p.w + bf;
        float cs = g_csum[(size_t)grow * 256 + Q];
        float sig_i = 1.0f / (1.0f + __expf(-iv));
        float sig_o = 1.0f / (1.0f + __expf(-ov));
        float sig_f = 1.0f / (1.0f + __expf(-fv));
        float c_new = sig_i * tanhf(uv) + sig_f * cs;
        float h_new = sig_o * tanhf(c_new);
        out[(size_t)grow * 256 + Q] = h_new;
        out[(size_t)N_NODES * 256 + (size_t)grow * 256 + Q] = c_new;
    }
}

// ---------------------------------------------------------------------------
// kernel_launch
// ---------------------------------------------------------------------------
extern "C" void kernel_launch(void* const* d_in, const int* in_sizes, int n_in,
                              void* d_out, int out_size) {
    const float* x     = (const float*)d_in[0];
    const float* h     = (const float*)d_in[1];
    const float* c     = (const float*)d_in[2];
    const int*   src   = (const int*)d_in[3];
    const int*   dst   = (const int*)d_in[4];
    const float* W_iou = (const float*)d_in[5];
    const float* U_iou = (const float*)d_in[6];
    const float* b_iou = (const float*)d_in[7];
    const float* U_f_w = (const float*)d_in[8];
    const float* U_f_b = (const float*)d_in[9];
    float* out = (float*)d_out;

    cudaFuncSetAttribute(gemm_fused_kernel,
                         cudaFuncAttributeMaxDynamicSharedMemorySize, SM_BYTES);

    build_B_kernel<<<(JDIM * KDIM + 255) / 256, 256>>>(W_iou, U_iou, U_f_w);

    {
        size_t n4 = (size_t)N_NODES * H / 4;
        zero_sums_kernel<<<(unsigned)((n4 + 255) / 256), 256>>>();
    }
    {
        size_t nt = (size_t)E_EDGES * (H / 4);
        scatter_kernel<<<(unsigned)((nt + 255) / 256), 256>>>(h, c, src, dst);
    }
    {
        dim3 grid(JDIM / TBJ, (N_NODES + TBM - 1) / TBM);   // (8, 1563)
        gemm_fused_kernel<<<grid, 256, SM_BYTES>>>(x, b_iou, U_f_b, out);
    }
}